// round 1
// baseline (speedup 1.0000x reference)
#include <cuda_runtime.h>
#include <cstdint>

// Problem constants
#define BATCH 8
#define NPIX  4096          // 64*64
#define CIN   256
#define DHEAD 32
#define MROWS (BATCH*NPIX)  // 32768

// Tiles
#define QT 64               // q rows per block (attention)
#define MT 64               // k/v rows per inner tile

// Scratch (device globals; no runtime allocation allowed)
__device__ float g_q[MROWS * DHEAD];
__device__ float g_k[MROWS * DHEAD];
__device__ float g_v[MROWS * DHEAD];
__device__ float g_attn[MROWS * DHEAD];

// ---------------------------------------------------------------------------
// Kernel 1: QKV projection.  X[32768,256] @ {Wq,Wk,Wv}[256,32] + bias, ReLU.
// Block: 256 threads, 64 rows, all 96 output cols. k-chunks of 32.
// ---------------------------------------------------------------------------
__global__ void qkv_kernel(const float* __restrict__ x,
                           const float* __restrict__ Wq, const float* __restrict__ bq,
                           const float* __restrict__ Wk, const float* __restrict__ bk,
                           const float* __restrict__ Wv, const float* __restrict__ bv)
{
    __shared__ float Xs[64][33];     // padded to kill bank conflicts
    __shared__ float Ws[32][96];     // [kk][col]: cols 0-31 q, 32-63 k, 64-95 v

    const int tid = threadIdx.x;
    const int tx = tid & 15;         // 16 col-groups of 6 cols
    const int ty = tid >> 4;         // 16 row-groups of 4 rows
    const int row0 = blockIdx.x * 64;

    float acc[4][6];
#pragma unroll
    for (int i = 0; i < 4; i++)
#pragma unroll
        for (int j = 0; j < 6; j++) acc[i][j] = 0.f;

    for (int kc = 0; kc < CIN; kc += 32) {
        // load X tile (coalesced float4, scalar smem stores due to pad)
#pragma unroll
        for (int it = 0; it < 2; it++) {
            int i = tid + it * 256;           // 0..511
            int r = i >> 3, c4 = i & 7;
            float4 v = *(const float4*)(x + (size_t)(row0 + r) * CIN + kc + c4 * 4);
            float* xp = &Xs[r][c4 * 4];
            xp[0] = v.x; xp[1] = v.y; xp[2] = v.z; xp[3] = v.w;
        }
        // load weight chunk: each thread one float4 per matrix
        {
            int kk = tid >> 3, j4 = tid & 7;
            *(float4*)&Ws[kk][j4 * 4]      = *(const float4*)(Wq + (size_t)(kc + kk) * DHEAD + j4 * 4);
            *(float4*)&Ws[kk][32 + j4 * 4] = *(const float4*)(Wk + (size_t)(kc + kk) * DHEAD + j4 * 4);
            *(float4*)&Ws[kk][64 + j4 * 4] = *(const float4*)(Wv + (size_t)(kc + kk) * DHEAD + j4 * 4);
        }
        __syncthreads();

#pragma unroll
        for (int kk = 0; kk < 32; kk++) {
            float a[4], w[6];
#pragma unroll
            for (int i = 0; i < 4; i++) a[i] = Xs[ty * 4 + i][kk];
#pragma unroll
            for (int j = 0; j < 6; j++) w[j] = Ws[kk][tx * 6 + j];
#pragma unroll
            for (int i = 0; i < 4; i++)
#pragma unroll
                for (int j = 0; j < 6; j++) acc[i][j] += a[i] * w[j];
        }
        __syncthreads();
    }

    // epilogue: bias + ReLU, route to q/k/v scratch
#pragma unroll
    for (int i = 0; i < 4; i++) {
        int row = row0 + ty * 4 + i;
#pragma unroll
        for (int j = 0; j < 6; j++) {
            int col = tx * 6 + j;
            float bias; float* dst;
            if (col < 32)      { bias = bq[col];      dst = g_q + (size_t)row * DHEAD + col; }
            else if (col < 64) { bias = bk[col - 32]; dst = g_k + (size_t)row * DHEAD + (col - 32); }
            else               { bias = bv[col - 64]; dst = g_v + (size_t)row * DHEAD + (col - 64); }
            *dst = fmaxf(acc[i][j] + bias, 0.f);
        }
    }
}

// ---------------------------------------------------------------------------
// Kernel 2: flash attention (no masking, no scale factor — matches reference).
// Grid: (NPIX/QT, BATCH). Block 256 threads.
//   GEMM1 layout: 16x16 threads, each 4 q-rows x 4 m-cols.
//   GEMM2 layout: 8(tx2: 4 dv) x 32(ty2: 2 rows).
// ---------------------------------------------------------------------------
__global__ void attn_kernel()
{
    __shared__ float Qs[QT][DHEAD];        // 8KB
    __shared__ float Kst[DHEAD][MT];       // 8KB, K transposed: [d][m]
    __shared__ float Vs[MT][DHEAD];        // 8KB
    __shared__ float Ps[QT][MT + 1];       // 16.25KB, padded
    __shared__ float scale_s[QT];
    __shared__ float l_s[QT];

    const int b  = blockIdx.y;
    const int qt = blockIdx.x;
    const int tid = threadIdx.x;
    const int tx  = tid & 15, ty  = tid >> 4;   // GEMM1
    const int tx2 = tid & 7,  ty2 = tid >> 3;   // GEMM2
    const int rq = ty * 4, cm = tx * 4;
    const int ry = ty2 * 2, dv = tx2 * 4;

    const float* qg = g_q + ((size_t)b * NPIX + (size_t)qt * QT) * DHEAD;
    const float* kg = g_k + (size_t)b * NPIX * DHEAD;
    const float* vg = g_v + (size_t)b * NPIX * DHEAD;

    // load Q tile once
#pragma unroll
    for (int it = 0; it < 2; it++) {
        int i = tid + it * 256;               // 0..511 float4s
        int r = i >> 3, c4 = i & 7;
        *(float4*)&Qs[r][c4 * 4] = *(const float4*)(qg + (size_t)r * DHEAD + c4 * 4);
    }

    float m_i[4], l_i[4];
#pragma unroll
    for (int i = 0; i < 4; i++) { m_i[i] = -1e30f; l_i[i] = 0.f; }
    float4 Oa0 = make_float4(0.f, 0.f, 0.f, 0.f);
    float4 Oa1 = make_float4(0.f, 0.f, 0.f, 0.f);

    __syncthreads();

    for (int mt = 0; mt < NPIX / MT; mt++) {
        const float* kt = kg + (size_t)mt * MT * DHEAD;
        const float* vt = vg + (size_t)mt * MT * DHEAD;
        // load K (transposed into Kst) and V
#pragma unroll
        for (int it = 0; it < 2; it++) {
            int i = tid + it * 256;
            int r = i >> 3, c4 = i & 7;
            float4 kv4 = *(const float4*)(kt + (size_t)r * DHEAD + c4 * 4);
            Kst[c4 * 4 + 0][r] = kv4.x;
            Kst[c4 * 4 + 1][r] = kv4.y;
            Kst[c4 * 4 + 2][r] = kv4.z;
            Kst[c4 * 4 + 3][r] = kv4.w;
            *(float4*)&Vs[r][c4 * 4] = *(const float4*)(vt + (size_t)r * DHEAD + c4 * 4);
        }
        __syncthreads();

        // ---- GEMM1: S = Q K^T (64x64), per-thread 4x4 ----
        float s[4][4];
#pragma unroll
        for (int i = 0; i < 4; i++)
#pragma unroll
            for (int j = 0; j < 4; j++) s[i][j] = 0.f;

#pragma unroll
        for (int d4 = 0; d4 < DHEAD / 4; d4++) {
            float4 kv0 = *(const float4*)&Kst[d4 * 4 + 0][cm];
            float4 kv1 = *(const float4*)&Kst[d4 * 4 + 1][cm];
            float4 kv2 = *(const float4*)&Kst[d4 * 4 + 2][cm];
            float4 kv3 = *(const float4*)&Kst[d4 * 4 + 3][cm];
#pragma unroll
            for (int i = 0; i < 4; i++) {
                float4 qv = *(const float4*)&Qs[rq + i][d4 * 4];
                s[i][0] += qv.x * kv0.x; s[i][1] += qv.x * kv0.y; s[i][2] += qv.x * kv0.z; s[i][3] += qv.x * kv0.w;
                s[i][0] += qv.y * kv1.x; s[i][1] += qv.y * kv1.y; s[i][2] += qv.y * kv1.z; s[i][3] += qv.y * kv1.w;
                s[i][0] += qv.z * kv2.x; s[i][1] += qv.z * kv2.y; s[i][2] += qv.z * kv2.z; s[i][3] += qv.z * kv2.w;
                s[i][0] += qv.w * kv3.x; s[i][1] += qv.w * kv3.y; s[i][2] += qv.w * kv3.z; s[i][3] += qv.w * kv3.w;
            }
        }

        // ---- online softmax (per q-row, reduce across 16 tx lanes) ----
#pragma unroll
        for (int i = 0; i < 4; i++) {
            float rm = fmaxf(fmaxf(s[i][0], s[i][1]), fmaxf(s[i][2], s[i][3]));
            rm = fmaxf(rm, __shfl_xor_sync(0xffffffffu, rm, 1));
            rm = fmaxf(rm, __shfl_xor_sync(0xffffffffu, rm, 2));
            rm = fmaxf(rm, __shfl_xor_sync(0xffffffffu, rm, 4));
            rm = fmaxf(rm, __shfl_xor_sync(0xffffffffu, rm, 8));
            float newm = fmaxf(m_i[i], rm);
            float corr = __expf(m_i[i] - newm);
            float psum = 0.f;
#pragma unroll
            for (int j = 0; j < 4; j++) {
                float p = __expf(s[i][j] - newm);
                s[i][j] = p;
                psum += p;
            }
            psum += __shfl_xor_sync(0xffffffffu, psum, 1);
            psum += __shfl_xor_sync(0xffffffffu, psum, 2);
            psum += __shfl_xor_sync(0xffffffffu, psum, 4);
            psum += __shfl_xor_sync(0xffffffffu, psum, 8);
            l_i[i] = l_i[i] * corr + psum;
            m_i[i] = newm;
            if (tx == 0) scale_s[rq + i] = corr;
#pragma unroll
            for (int j = 0; j < 4; j++) Ps[rq + i][cm + j] = s[i][j];
        }
        __syncthreads();

        // ---- rescale O, GEMM2: O += P V (64x32), per-thread 2 rows x 4 dv ----
        {
            float c0 = scale_s[ry], c1 = scale_s[ry + 1];
            Oa0.x *= c0; Oa0.y *= c0; Oa0.z *= c0; Oa0.w *= c0;
            Oa1.x *= c1; Oa1.y *= c1; Oa1.z *= c1; Oa1.w *= c1;
        }
#pragma unroll 4
        for (int m = 0; m < MT; m++) {
            float4 vv = *(const float4*)&Vs[m][dv];
            float p0 = Ps[ry][m];
            float p1 = Ps[ry + 1][m];
            Oa0.x += p0 * vv.x; Oa0.y += p0 * vv.y; Oa0.z += p0 * vv.z; Oa0.w += p0 * vv.w;
            Oa1.x += p1 * vv.x; Oa1.y += p1 * vv.y; Oa1.z += p1 * vv.z; Oa1.w += p1 * vv.w;
        }
        __syncthreads();
    }

    // epilogue: divide by l, write out
    if (tx == 0) {
#pragma unroll
        for (int i = 0; i < 4; i++) l_s[rq + i] = l_i[i];
    }
    __syncthreads();
    {
        float inv0 = 1.f / l_s[ry];
        float inv1 = 1.f / l_s[ry + 1];
        Oa0.x *= inv0; Oa0.y *= inv0; Oa0.z *= inv0; Oa0.w *= inv0;
        Oa1.x *= inv1; Oa1.y *= inv1; Oa1.z *= inv1; Oa1.w *= inv1;
        float* dst = g_attn + ((size_t)b * NPIX + (size_t)qt * QT) * DHEAD;
        *(float4*)(dst + (size_t)(ry + 0) * DHEAD + dv) = Oa0;
        *(float4*)(dst + (size_t)(ry + 1) * DHEAD + dv) = Oa1;
    }
}

// ---------------------------------------------------------------------------
// Kernel 3: output projection. A[32768,32] @ Wo[32,256] + bo, ReLU -> out.
// Block: 256 threads, 64 rows. Per-thread 4 rows x 4 float4 col-groups.
// ---------------------------------------------------------------------------
__global__ void proj_kernel(const float* __restrict__ Wo,
                            const float* __restrict__ bo,
                            float* __restrict__ out)
{
    __shared__ float As[64][33];
    __shared__ float Wos[32][256];   // 32KB
    __shared__ float bos[256];

    const int tid = threadIdx.x;
    const int tx = tid & 15, ty = tid >> 4;
    const int row0 = blockIdx.x * 64;

    // load A tile
#pragma unroll
    for (int it = 0; it < 2; it++) {
        int i = tid + it * 256;
        int r = i >> 3, c4 = i & 7;
        float4 v = *(const float4*)(g_attn + (size_t)(row0 + r) * DHEAD + c4 * 4);
        float* ap = &As[r][c4 * 4];
        ap[0] = v.x; ap[1] = v.y; ap[2] = v.z; ap[3] = v.w;
    }
    // load Wo (2048 float4) + bias
#pragma unroll
    for (int it = 0; it < 8; it++) {
        int i = tid + it * 256;
        int kk = i >> 6, c4 = i & 63;
        *(float4*)&Wos[kk][c4 * 4] = *(const float4*)(Wo + (size_t)kk * 256 + c4 * 4);
    }
    bos[tid] = bo[tid];
    __syncthreads();

    // acc[i][g] over cols g*64 + tx*4 .. +3
    float4 acc[4][4];
#pragma unroll
    for (int g = 0; g < 4; g++) {
        float4 bv = *(const float4*)&bos[g * 64 + tx * 4];
#pragma unroll
        for (int i = 0; i < 4; i++) acc[i][g] = bv;
    }

#pragma unroll
    for (int kk = 0; kk < 32; kk++) {
        float a[4];
#pragma unroll
        for (int i = 0; i < 4; i++) a[i] = As[ty * 4 + i][kk];
#pragma unroll
        for (int g = 0; g < 4; g++) {
            float4 w = *(const float4*)&Wos[kk][g * 64 + tx * 4];
#pragma unroll
            for (int i = 0; i < 4; i++) {
                acc[i][g].x += a[i] * w.x;
                acc[i][g].y += a[i] * w.y;
                acc[i][g].z += a[i] * w.z;
                acc[i][g].w += a[i] * w.w;
            }
        }
    }

#pragma unroll
    for (int i = 0; i < 4; i++) {
        size_t rowbase = (size_t)(row0 + ty * 4 + i) * 256;
#pragma unroll
        for (int g = 0; g < 4; g++) {
            float4 v = acc[i][g];
            v.x = fmaxf(v.x, 0.f); v.y = fmaxf(v.y, 0.f);
            v.z = fmaxf(v.z, 0.f); v.w = fmaxf(v.w, 0.f);
            *(float4*)(out + rowbase + g * 64 + tx * 4) = v;
        }
    }
}

// ---------------------------------------------------------------------------
extern "C" void kernel_launch(void* const* d_in, const int* in_sizes, int n_in,
                              void* d_out, int out_size)
{
    const float* x  = (const float*)d_in[0];
    const float* Wq = (const float*)d_in[1];
    const float* bq = (const float*)d_in[2];
    const float* Wk = (const float*)d_in[3];
    const float* bk = (const float*)d_in[4];
    const float* Wv = (const float*)d_in[5];
    const float* bv = (const float*)d_in[6];
    const float* Wo = (const float*)d_in[7];
    const float* bo = (const float*)d_in[8];
    float* out = (float*)d_out;

    qkv_kernel<<<MROWS / 64, 256>>>(x, Wq, bq, Wk, bk, Wv, bv);
    attn_kernel<<<dim3(NPIX / QT, BATCH), 256>>>();
    proj_kernel<<<MROWS / 64, 256>>>(Wo, bo, out);
}

// round 2
// speedup vs baseline: 3.1833x; 3.1833x over previous
#include <cuda_runtime.h>
#include <cstdint>

// Problem constants
#define BATCH 8
#define NPIX  4096          // 64*64
#define CIN   256
#define DHEAD 32
#define MROWS (BATCH*NPIX)  // 32768

#define QT 128              // q rows per block (4 warps x 32 rows)
#define MT 64               // k/v rows per inner tile

#define KS_STRIDE 36        // 36 % 32 == 4  -> conflict-free B(K) frag loads
#define VS_STRIDE 40        // 40 % 32 == 8  -> conflict-free B(V) frag loads
#define PS_STRIDE 68        // 68 % 32 == 4  -> conflict-free A(P) frag loads

// Scratch (device globals; no runtime allocation allowed)
__device__ float g_q[MROWS * DHEAD];
__device__ float g_k[MROWS * DHEAD];
__device__ float g_v[MROWS * DHEAD];
__device__ float g_attn[MROWS * DHEAD];

// ---------------------------------------------------------------------------
// helpers
// ---------------------------------------------------------------------------
__device__ __forceinline__ uint32_t f2tf(float f) {
    uint32_t u;
    asm("cvt.rna.tf32.f32 %0, %1;" : "=r"(u) : "f"(f));
    return u;
}

__device__ __forceinline__ void mma_tf32(float* d,
                                         const uint32_t* a,
                                         const uint32_t* b,
                                         const float* c)
{
    asm("mma.sync.aligned.m16n8k8.row.col.f32.tf32.tf32.f32 "
        "{%0,%1,%2,%3}, {%4,%5,%6,%7}, {%8,%9}, {%10,%11,%12,%13};"
        : "=f"(d[0]), "=f"(d[1]), "=f"(d[2]), "=f"(d[3])
        : "r"(a[0]), "r"(a[1]), "r"(a[2]), "r"(a[3]),
          "r"(b[0]), "r"(b[1]),
          "f"(c[0]), "f"(c[1]), "f"(c[2]), "f"(c[3]));
}

// ---------------------------------------------------------------------------
// Kernel 1: QKV projection.  X[32768,256] @ {Wq,Wk,Wv}[256,32] + bias, ReLU.
// ---------------------------------------------------------------------------
__global__ void qkv_kernel(const float* __restrict__ x,
                           const float* __restrict__ Wq, const float* __restrict__ bq,
                           const float* __restrict__ Wk, const float* __restrict__ bk,
                           const float* __restrict__ Wv, const float* __restrict__ bv)
{
    __shared__ float Xs[64][33];
    __shared__ float Ws[32][96];

    const int tid = threadIdx.x;
    const int tx = tid & 15;
    const int ty = tid >> 4;
    const int row0 = blockIdx.x * 64;

    float acc[4][6];
#pragma unroll
    for (int i = 0; i < 4; i++)
#pragma unroll
        for (int j = 0; j < 6; j++) acc[i][j] = 0.f;

    for (int kc = 0; kc < CIN; kc += 32) {
#pragma unroll
        for (int it = 0; it < 2; it++) {
            int i = tid + it * 256;
            int r = i >> 3, c4 = i & 7;
            float4 v = *(const float4*)(x + (size_t)(row0 + r) * CIN + kc + c4 * 4);
            float* xp = &Xs[r][c4 * 4];
            xp[0] = v.x; xp[1] = v.y; xp[2] = v.z; xp[3] = v.w;
        }
        {
            int kk = tid >> 3, j4 = tid & 7;
            *(float4*)&Ws[kk][j4 * 4]      = *(const float4*)(Wq + (size_t)(kc + kk) * DHEAD + j4 * 4);
            *(float4*)&Ws[kk][32 + j4 * 4] = *(const float4*)(Wk + (size_t)(kc + kk) * DHEAD + j4 * 4);
            *(float4*)&Ws[kk][64 + j4 * 4] = *(const float4*)(Wv + (size_t)(kc + kk) * DHEAD + j4 * 4);
        }
        __syncthreads();

#pragma unroll
        for (int kk = 0; kk < 32; kk++) {
            float a[4], w[6];
#pragma unroll
            for (int i = 0; i < 4; i++) a[i] = Xs[ty * 4 + i][kk];
#pragma unroll
            for (int j = 0; j < 6; j++) w[j] = Ws[kk][tx * 6 + j];
#pragma unroll
            for (int i = 0; i < 4; i++)
#pragma unroll
                for (int j = 0; j < 6; j++) acc[i][j] += a[i] * w[j];
        }
        __syncthreads();
    }

#pragma unroll
    for (int i = 0; i < 4; i++) {
        int row = row0 + ty * 4 + i;
#pragma unroll
        for (int j = 0; j < 6; j++) {
            int col = tx * 6 + j;
            float bias; float* dst;
            if (col < 32)      { bias = bq[col];      dst = g_q + (size_t)row * DHEAD + col; }
            else if (col < 64) { bias = bk[col - 32]; dst = g_k + (size_t)row * DHEAD + (col - 32); }
            else               { bias = bv[col - 64]; dst = g_v + (size_t)row * DHEAD + (col - 64); }
            *dst = fmaxf(acc[i][j] + bias, 0.f);
        }
    }
}

// ---------------------------------------------------------------------------
// Kernel 2: flash attention with tf32 mma.sync tensor cores.
// Grid (NPIX/QT, BATCH) = (32, 8). Block 128 threads = 4 warps.
// Each warp: 32 q rows = two m16 A-tiles. Inner tile: 64 k/v rows.
//   mma1: S(16x64) = Q(16x32) K^T  -> 8 nblocks x 4 ksteps per A-tile
//   softmax online, in registers (+shfl)
//   mma2: O(16x32) += P(16x64) V   -> P staged via per-warp smem tile
// ---------------------------------------------------------------------------
__global__ void __launch_bounds__(128) attn_kernel()
{
    __shared__ float Ks[MT * KS_STRIDE];       // K tile [m][d], tf32 bits
    __shared__ float Vs[MT * VS_STRIDE];       // V tile [m][d], tf32 bits
    __shared__ float Ps[4][16 * PS_STRIDE];    // per-warp P tile, tf32 bits

    const int b   = blockIdx.y;
    const int qt  = blockIdx.x;
    const int tid = threadIdx.x;
    const int warp = tid >> 5, lane = tid & 31;
    const int gid = lane >> 2, tig = lane & 3;   // group id (row), thread-in-group (col)

    const float* qg = g_q + ((size_t)b * NPIX + (size_t)qt * QT + warp * 32) * DHEAD;
    const float* kg = g_k + (size_t)b * NPIX * DHEAD;
    const float* vg = g_v + (size_t)b * NPIX * DHEAD;

    // ---- preload Q fragments (tf32), once per block ----
    uint32_t qa[2][4][4];
#pragma unroll
    for (int h = 0; h < 2; h++)
#pragma unroll
        for (int ks = 0; ks < 4; ks++) {
            int r0 = h * 16 + gid;
            qa[h][ks][0] = f2tf(qg[(size_t)(r0)     * DHEAD + ks * 8 + tig]);
            qa[h][ks][1] = f2tf(qg[(size_t)(r0 + 8) * DHEAD + ks * 8 + tig]);
            qa[h][ks][2] = f2tf(qg[(size_t)(r0)     * DHEAD + ks * 8 + tig + 4]);
            qa[h][ks][3] = f2tf(qg[(size_t)(r0 + 8) * DHEAD + ks * 8 + tig + 4]);
        }

    float O[2][4][4];
#pragma unroll
    for (int h = 0; h < 2; h++)
#pragma unroll
        for (int db = 0; db < 4; db++)
#pragma unroll
            for (int r = 0; r < 4; r++) O[h][db][r] = 0.f;

    float mi[2][2], li[2][2];
#pragma unroll
    for (int h = 0; h < 2; h++) { mi[h][0] = mi[h][1] = -1e30f; li[h][0] = li[h][1] = 0.f; }

    for (int mt = 0; mt < NPIX / MT; mt++) {
        const float* kt = kg + (size_t)mt * MT * DHEAD;
        const float* vt = vg + (size_t)mt * MT * DHEAD;

        // ---- load K/V tiles into smem (tf32-rounded bit patterns) ----
#pragma unroll
        for (int it = 0; it < 4; it++) {
            int i = tid + it * 128;          // float4 index 0..511
            int r = i >> 3, c4 = i & 7;
            float4 kv = *(const float4*)(kt + (size_t)r * DHEAD + c4 * 4);
            float4 vv = *(const float4*)(vt + (size_t)r * DHEAD + c4 * 4);
            float4 kb, vb;
            kb.x = __uint_as_float(f2tf(kv.x)); kb.y = __uint_as_float(f2tf(kv.y));
            kb.z = __uint_as_float(f2tf(kv.z)); kb.w = __uint_as_float(f2tf(kv.w));
            vb.x = __uint_as_float(f2tf(vv.x)); vb.y = __uint_as_float(f2tf(vv.y));
            vb.z = __uint_as_float(f2tf(vv.z)); vb.w = __uint_as_float(f2tf(vv.w));
            *(float4*)&Ks[r * KS_STRIDE + c4 * 4] = kb;
            *(float4*)&Vs[r * VS_STRIDE + c4 * 4] = vb;
        }
        __syncthreads();

        // ---- mma1: S = Q K^T ----
        float S[2][8][4];
#pragma unroll
        for (int h = 0; h < 2; h++)
#pragma unroll
            for (int nb = 0; nb < 8; nb++)
#pragma unroll
                for (int r = 0; r < 4; r++) S[h][nb][r] = 0.f;

#pragma unroll
        for (int nb = 0; nb < 8; nb++) {
#pragma unroll
            for (int ks = 0; ks < 4; ks++) {
                uint32_t bf[2];
                bf[0] = __float_as_uint(Ks[(nb * 8 + gid) * KS_STRIDE + ks * 8 + tig]);
                bf[1] = __float_as_uint(Ks[(nb * 8 + gid) * KS_STRIDE + ks * 8 + tig + 4]);
                mma_tf32(S[0][nb], qa[0][ks], bf, S[0][nb]);
                mma_tf32(S[1][nb], qa[1][ks], bf, S[1][nb]);
            }
        }

        // ---- per-half: online softmax + stage P + mma2 ----
#pragma unroll
        for (int h = 0; h < 2; h++) {
            // row stats (rows gid and gid+8 of this half's 16-row tile)
            float rm0 = -1e30f, rm1 = -1e30f;
#pragma unroll
            for (int nb = 0; nb < 8; nb++) {
                rm0 = fmaxf(rm0, fmaxf(S[h][nb][0], S[h][nb][1]));
                rm1 = fmaxf(rm1, fmaxf(S[h][nb][2], S[h][nb][3]));
            }
            rm0 = fmaxf(rm0, __shfl_xor_sync(0xffffffffu, rm0, 1));
            rm0 = fmaxf(rm0, __shfl_xor_sync(0xffffffffu, rm0, 2));
            rm1 = fmaxf(rm1, __shfl_xor_sync(0xffffffffu, rm1, 1));
            rm1 = fmaxf(rm1, __shfl_xor_sync(0xffffffffu, rm1, 2));

            float nm0 = fmaxf(mi[h][0], rm0);
            float nm1 = fmaxf(mi[h][1], rm1);
            float corr0 = __expf(mi[h][0] - nm0);
            float corr1 = __expf(mi[h][1] - nm1);
            mi[h][0] = nm0; mi[h][1] = nm1;

            float sum0 = 0.f, sum1 = 0.f;
#pragma unroll
            for (int nb = 0; nb < 8; nb++) {
                float p0 = __expf(S[h][nb][0] - nm0);
                float p1 = __expf(S[h][nb][1] - nm0);
                float p2 = __expf(S[h][nb][2] - nm1);
                float p3 = __expf(S[h][nb][3] - nm1);
                sum0 += p0 + p1;
                sum1 += p2 + p3;
                float2 st0, st1;
                st0.x = __uint_as_float(f2tf(p0)); st0.y = __uint_as_float(f2tf(p1));
                st1.x = __uint_as_float(f2tf(p2)); st1.y = __uint_as_float(f2tf(p3));
                *(float2*)&Ps[warp][gid       * PS_STRIDE + nb * 8 + 2 * tig] = st0;
                *(float2*)&Ps[warp][(gid + 8) * PS_STRIDE + nb * 8 + 2 * tig] = st1;
            }
            sum0 += __shfl_xor_sync(0xffffffffu, sum0, 1);
            sum0 += __shfl_xor_sync(0xffffffffu, sum0, 2);
            sum1 += __shfl_xor_sync(0xffffffffu, sum1, 1);
            sum1 += __shfl_xor_sync(0xffffffffu, sum1, 2);
            li[h][0] = li[h][0] * corr0 + sum0;
            li[h][1] = li[h][1] * corr1 + sum1;

            // rescale O accumulators (rows gid -> regs 0,1; rows gid+8 -> regs 2,3)
#pragma unroll
            for (int db = 0; db < 4; db++) {
                O[h][db][0] *= corr0; O[h][db][1] *= corr0;
                O[h][db][2] *= corr1; O[h][db][3] *= corr1;
            }
            __syncwarp();

            // mma2: O[h] += P V  (k = 64 -> 8 ksteps)
#pragma unroll
            for (int ks2 = 0; ks2 < 8; ks2++) {
                uint32_t pa[4];
                pa[0] = __float_as_uint(Ps[warp][gid       * PS_STRIDE + ks2 * 8 + tig]);
                pa[1] = __float_as_uint(Ps[warp][(gid + 8) * PS_STRIDE + ks2 * 8 + tig]);
                pa[2] = __float_as_uint(Ps[warp][gid       * PS_STRIDE + ks2 * 8 + tig + 4]);
                pa[3] = __float_as_uint(Ps[warp][(gid + 8) * PS_STRIDE + ks2 * 8 + tig + 4]);
#pragma unroll
                for (int db = 0; db < 4; db++) {
                    uint32_t vb[2];
                    vb[0] = __float_as_uint(Vs[(ks2 * 8 + tig)     * VS_STRIDE + db * 8 + gid]);
                    vb[1] = __float_as_uint(Vs[(ks2 * 8 + tig + 4) * VS_STRIDE + db * 8 + gid]);
                    mma_tf32(O[h][db], pa, vb, O[h][db]);
                }
            }
            __syncwarp();   // Ps reused by next half
        }
        __syncthreads();    // Ks/Vs reused by next tile
    }

    // ---- epilogue: divide by l, store O ----
#pragma unroll
    for (int h = 0; h < 2; h++) {
        float inv0 = 1.f / li[h][0];
        float inv1 = 1.f / li[h][1];
        size_t base = (size_t)b * NPIX + (size_t)qt * QT + warp * 32 + h * 16;
#pragma unroll
        for (int db = 0; db < 4; db++) {
            float2 o0, o1;
            o0.x = O[h][db][0] * inv0; o0.y = O[h][db][1] * inv0;
            o1.x = O[h][db][2] * inv1; o1.y = O[h][db][3] * inv1;
            *(float2*)(g_attn + (base + gid)     * DHEAD + db * 8 + 2 * tig) = o0;
            *(float2*)(g_attn + (base + gid + 8) * DHEAD + db * 8 + 2 * tig) = o1;
        }
    }
}

// ---------------------------------------------------------------------------
// Kernel 3: output projection. A[32768,32] @ Wo[32,256] + bo, ReLU -> out.
// ---------------------------------------------------------------------------
__global__ void proj_kernel(const float* __restrict__ Wo,
                            const float* __restrict__ bo,
                            float* __restrict__ out)
{
    __shared__ float As[64][33];
    __shared__ float Wos[32][256];
    __shared__ float bos[256];

    const int tid = threadIdx.x;
    const int tx = tid & 15, ty = tid >> 4;
    const int row0 = blockIdx.x * 64;

#pragma unroll
    for (int it = 0; it < 2; it++) {
        int i = tid + it * 256;
        int r = i >> 3, c4 = i & 7;
        float4 v = *(const float4*)(g_attn + (size_t)(row0 + r) * DHEAD + c4 * 4);
        float* ap = &As[r][c4 * 4];
        ap[0] = v.x; ap[1] = v.y; ap[2] = v.z; ap[3] = v.w;
    }
#pragma unroll
    for (int it = 0; it < 8; it++) {
        int i = tid + it * 256;
        int kk = i >> 6, c4 = i & 63;
        *(float4*)&Wos[kk][c4 * 4] = *(const float4*)(Wo + (size_t)kk * 256 + c4 * 4);
    }
    bos[tid] = bo[tid];
    __syncthreads();

    float4 acc[4][4];
#pragma unroll
    for (int g = 0; g < 4; g++) {
        float4 bv = *(const float4*)&bos[g * 64 + tx * 4];
#pragma unroll
        for (int i = 0; i < 4; i++) acc[i][g] = bv;
    }

#pragma unroll
    for (int kk = 0; kk < 32; kk++) {
        float a[4];
#pragma unroll
        for (int i = 0; i < 4; i++) a[i] = As[ty * 4 + i][kk];
#pragma unroll
        for (int g = 0; g < 4; g++) {
            float4 w = *(const float4*)&Wos[kk][g * 64 + tx * 4];
#pragma unroll
            for (int i = 0; i < 4; i++) {
                acc[i][g].x += a[i] * w.x;
                acc[i][g].y += a[i] * w.y;
                acc[i][g].z += a[i] * w.z;
                acc[i][g].w += a[i] * w.w;
            }
        }
    }

#pragma unroll
    for (int i = 0; i < 4; i++) {
        size_t rowbase = (size_t)(row0 + ty * 4 + i) * 256;
#pragma unroll
        for (int g = 0; g < 4; g++) {
            float4 v = acc[i][g];
            v.x = fmaxf(v.x, 0.f); v.y = fmaxf(v.y, 0.f);
            v.z = fmaxf(v.z, 0.f); v.w = fmaxf(v.w, 0.f);
            *(float4*)(out + rowbase + g * 64 + tx * 4) = v;
        }
    }
}

// ---------------------------------------------------------------------------
extern "C" void kernel_launch(void* const* d_in, const int* in_sizes, int n_in,
                              void* d_out, int out_size)
{
    const float* x  = (const float*)d_in[0];
    const float* Wq = (const float*)d_in[1];
    const float* bq = (const float*)d_in[2];
    const float* Wk = (const float*)d_in[3];
    const float* bk = (const float*)d_in[4];
    const float* Wv = (const float*)d_in[5];
    const float* bv = (const float*)d_in[6];
    const float* Wo = (const float*)d_in[7];
    const float* bo = (const float*)d_in[8];
    float* out = (float*)d_out;

    qkv_kernel<<<MROWS / 64, 256>>>(x, Wq, bq, Wk, bk, Wv, bv);
    attn_kernel<<<dim3(NPIX / QT, BATCH), 128>>>();
    proj_kernel<<<MROWS / 64, 256>>>(Wo, bo, out);
}

// round 3
// speedup vs baseline: 4.1019x; 1.2886x over previous
#include <cuda_runtime.h>
#include <cstdint>

// Problem constants
#define BATCH 8
#define NPIX  4096          // 64*64
#define CIN   256
#define DHEAD 32
#define MROWS (BATCH*NPIX)  // 32768

#define QT 128              // q rows per attn block (8 warps x 16 rows)
#define MT 64               // k/v rows per inner tile

#define KS_STR 36           // (nb*8+gid)*36 + ks*8+tig -> bank 4*gid+tig  (CF)
#define VS_STR 40           // (ks2*8+tig)*40 + db*8+gid -> bank 8*tig+gid (CF)
#define XS_STR 36
#define WQ_STR 104          // (ks*8+tig)*104 + nb*8+gid -> bank 8*tig+gid (CF)
#define WO_STR 136          // same residue mod 32 = 8   (CF)

// Scratch (device globals; no runtime allocation allowed)
__device__ float g_q[MROWS * DHEAD];
__device__ float g_k[MROWS * DHEAD];
__device__ float g_v[MROWS * DHEAD];
__device__ float g_attn[MROWS * DHEAD];

// ---------------------------------------------------------------------------
// helpers
// ---------------------------------------------------------------------------
__device__ __forceinline__ uint32_t f2tf(float f) {
    uint32_t u;
    asm("cvt.rna.tf32.f32 %0, %1;" : "=r"(u) : "f"(f));
    return u;
}
__device__ __forceinline__ float4 cvt4(float4 v) {
    float4 r;
    r.x = __uint_as_float(f2tf(v.x)); r.y = __uint_as_float(f2tf(v.y));
    r.z = __uint_as_float(f2tf(v.z)); r.w = __uint_as_float(f2tf(v.w));
    return r;
}
__device__ __forceinline__ void mma_tf32(float* d,
                                         const uint32_t* a,
                                         const uint32_t* b,
                                         const float* c)
{
    asm("mma.sync.aligned.m16n8k8.row.col.f32.tf32.tf32.f32 "
        "{%0,%1,%2,%3}, {%4,%5,%6,%7}, {%8,%9}, {%10,%11,%12,%13};"
        : "=f"(d[0]), "=f"(d[1]), "=f"(d[2]), "=f"(d[3])
        : "r"(a[0]), "r"(a[1]), "r"(a[2]), "r"(a[3]),
          "r"(b[0]), "r"(b[1]),
          "f"(c[0]), "f"(c[1]), "f"(c[2]), "f"(c[3]));
}

// ---------------------------------------------------------------------------
// Kernel 1: QKV projection with tf32 mma.
// X[32768,256] @ [Wq|Wk|Wv][256,96] + bias, ReLU -> g_q/g_k/g_v.
// Block 256 thr / 8 warps; tile M=128 (warp m16), N=96 (12 n8), K chunks of 32.
// ---------------------------------------------------------------------------
__global__ void __launch_bounds__(256) qkv_kernel(
    const float* __restrict__ x,
    const float* __restrict__ Wq, const float* __restrict__ bq,
    const float* __restrict__ Wk, const float* __restrict__ bk,
    const float* __restrict__ Wv, const float* __restrict__ bv)
{
    __shared__ float Xs[128 * XS_STR];     // 18.4 KB
    __shared__ float Wsm[32 * WQ_STR];     // 13.3 KB
    __shared__ float bsm[96];

    const int tid = threadIdx.x;
    const int warp = tid >> 5, lane = tid & 31;
    const int gid = lane >> 2, tig = lane & 3;
    const int row0 = blockIdx.x * 128;

    if (tid < 96) bsm[tid] = (tid < 32) ? bq[tid] : (tid < 64 ? bk[tid - 32] : bv[tid - 64]);

    float acc[12][4];
#pragma unroll
    for (int nb = 0; nb < 12; nb++)
#pragma unroll
        for (int r = 0; r < 4; r++) acc[nb][r] = 0.f;

    for (int kc = 0; kc < CIN; kc += 32) {
        // X tile: 128 rows x 32 cols (tf32-rounded)
#pragma unroll
        for (int it = 0; it < 4; it++) {
            int i = tid + it * 256;
            int r = i >> 3, c4 = i & 7;
            float4 v = *(const float4*)(x + (size_t)(row0 + r) * CIN + kc + c4 * 4);
            *(float4*)&Xs[r * XS_STR + c4 * 4] = cvt4(v);
        }
        // W chunk: 32 rows x 96 cols
        {
            int kk = tid >> 3, j4 = tid & 7;
            float4 a = *(const float4*)(Wq + (size_t)(kc + kk) * DHEAD + j4 * 4);
            float4 b = *(const float4*)(Wk + (size_t)(kc + kk) * DHEAD + j4 * 4);
            float4 c = *(const float4*)(Wv + (size_t)(kc + kk) * DHEAD + j4 * 4);
            *(float4*)&Wsm[kk * WQ_STR +      j4 * 4] = cvt4(a);
            *(float4*)&Wsm[kk * WQ_STR + 32 + j4 * 4] = cvt4(b);
            *(float4*)&Wsm[kk * WQ_STR + 64 + j4 * 4] = cvt4(c);
        }
        __syncthreads();

#pragma unroll
        for (int ks = 0; ks < 4; ks++) {
            uint32_t a[4];
            int xb = (warp * 16 + gid) * XS_STR + ks * 8 + tig;
            a[0] = __float_as_uint(Xs[xb]);
            a[1] = __float_as_uint(Xs[xb + 8 * XS_STR]);
            a[2] = __float_as_uint(Xs[xb + 4]);
            a[3] = __float_as_uint(Xs[xb + 8 * XS_STR + 4]);
#pragma unroll
            for (int nb = 0; nb < 12; nb++) {
                uint32_t bf[2];
                int wb = (ks * 8 + tig) * WQ_STR + nb * 8 + gid;
                bf[0] = __float_as_uint(Wsm[wb]);
                bf[1] = __float_as_uint(Wsm[wb + 4 * WQ_STR]);
                mma_tf32(acc[nb], a, bf, acc[nb]);
            }
        }
        __syncthreads();
    }

    // epilogue: bias + ReLU, route to q/k/v
#pragma unroll
    for (int nb = 0; nb < 12; nb++) {
        int c = nb * 8 + 2 * tig;
        float b0 = bsm[c], b1 = bsm[c + 1];
        int r0 = row0 + warp * 16 + gid;
        float* dst; int col;
        if (nb < 4)      { dst = g_q; col = c; }
        else if (nb < 8) { dst = g_k; col = c - 32; }
        else             { dst = g_v; col = c - 64; }
        float2 lo, hi;
        lo.x = fmaxf(acc[nb][0] + b0, 0.f); lo.y = fmaxf(acc[nb][1] + b1, 0.f);
        hi.x = fmaxf(acc[nb][2] + b0, 0.f); hi.y = fmaxf(acc[nb][3] + b1, 0.f);
        *(float2*)(dst + (size_t)r0 * DHEAD + col)       = lo;
        *(float2*)(dst + (size_t)(r0 + 8) * DHEAD + col) = hi;
    }
}

// ---------------------------------------------------------------------------
// Kernel 2: flash attention, tf32 mma, 8 warps, double-buffered K/V,
// P passed mma1->mma2 via register shuffles (no smem staging).
// Grid (32, 8). One wave: 256 CTAs at 2/SM.
// ---------------------------------------------------------------------------
__global__ void __launch_bounds__(256, 2) attn_kernel()
{
    __shared__ float Ks[2][MT * KS_STR];   // 2 x 9.2 KB
    __shared__ float Vs[2][MT * VS_STR];   // 2 x 10.2 KB

    const int b   = blockIdx.y;
    const int qt  = blockIdx.x;
    const int tid = threadIdx.x;
    const int warp = tid >> 5, lane = tid & 31;
    const int gid = lane >> 2, tig = lane & 3;
    const int hi  = tig & 1;
    const int srcA = (lane & 28) | (tig >> 1);
    const int srcB = srcA | 2;

    const float* qg = g_q + ((size_t)b * NPIX + (size_t)qt * QT + warp * 16) * DHEAD;
    const float* kg = g_k + (size_t)b * NPIX * DHEAD;
    const float* vg = g_v + (size_t)b * NPIX * DHEAD;

    // Q fragments (tf32), loaded once
    uint32_t qa[4][4];
#pragma unroll
    for (int ks = 0; ks < 4; ks++) {
        qa[ks][0] = f2tf(qg[(size_t)(gid)     * DHEAD + ks * 8 + tig]);
        qa[ks][1] = f2tf(qg[(size_t)(gid + 8) * DHEAD + ks * 8 + tig]);
        qa[ks][2] = f2tf(qg[(size_t)(gid)     * DHEAD + ks * 8 + tig + 4]);
        qa[ks][3] = f2tf(qg[(size_t)(gid + 8) * DHEAD + ks * 8 + tig + 4]);
    }

    float O[4][4];
#pragma unroll
    for (int db = 0; db < 4; db++)
#pragma unroll
        for (int r = 0; r < 4; r++) O[db][r] = 0.f;
    float mi0 = -1e30f, mi1 = -1e30f, li0 = 0.f, li1 = 0.f;

    float4 kpre[2], vpre[2];
    // prologue: load tile 0
#pragma unroll
    for (int it = 0; it < 2; it++) {
        int i = tid + it * 256;
        int r = i >> 3, c4 = i & 7;
        kpre[it] = *(const float4*)(kg + (size_t)r * DHEAD + c4 * 4);
        vpre[it] = *(const float4*)(vg + (size_t)r * DHEAD + c4 * 4);
    }
#pragma unroll
    for (int it = 0; it < 2; it++) {
        int i = tid + it * 256;
        int r = i >> 3, c4 = i & 7;
        *(float4*)&Ks[0][r * KS_STR + c4 * 4] = cvt4(kpre[it]);
        *(float4*)&Vs[0][r * VS_STR + c4 * 4] = cvt4(vpre[it]);
    }
    __syncthreads();

    for (int mt = 0; mt < NPIX / MT; mt++) {
        const int cur = mt & 1;

        // prefetch next tile from gmem (latency hidden behind compute)
        if (mt + 1 < NPIX / MT) {
            const float* kt = kg + (size_t)(mt + 1) * MT * DHEAD;
            const float* vt = vg + (size_t)(mt + 1) * MT * DHEAD;
#pragma unroll
            for (int it = 0; it < 2; it++) {
                int i = tid + it * 256;
                int r = i >> 3, c4 = i & 7;
                kpre[it] = *(const float4*)(kt + (size_t)r * DHEAD + c4 * 4);
                vpre[it] = *(const float4*)(vt + (size_t)r * DHEAD + c4 * 4);
            }
        }

        // ---- mma1: S(16x64) = Q K^T ----
        float S[8][4];
#pragma unroll
        for (int nb = 0; nb < 8; nb++)
#pragma unroll
            for (int r = 0; r < 4; r++) S[nb][r] = 0.f;
#pragma unroll
        for (int nb = 0; nb < 8; nb++) {
#pragma unroll
            for (int ks = 0; ks < 4; ks++) {
                uint32_t bf[2];
                int kb = (nb * 8 + gid) * KS_STR + ks * 8 + tig;
                bf[0] = __float_as_uint(Ks[cur][kb]);
                bf[1] = __float_as_uint(Ks[cur][kb + 4]);
                mma_tf32(S[nb], qa[ks], bf, S[nb]);
            }
        }

        // ---- online softmax (rows gid, gid+8) ----
        float rm0 = -1e30f, rm1 = -1e30f;
#pragma unroll
        for (int nb = 0; nb < 8; nb++) {
            rm0 = fmaxf(rm0, fmaxf(S[nb][0], S[nb][1]));
            rm1 = fmaxf(rm1, fmaxf(S[nb][2], S[nb][3]));
        }
        rm0 = fmaxf(rm0, __shfl_xor_sync(0xffffffffu, rm0, 1));
        rm0 = fmaxf(rm0, __shfl_xor_sync(0xffffffffu, rm0, 2));
        rm1 = fmaxf(rm1, __shfl_xor_sync(0xffffffffu, rm1, 1));
        rm1 = fmaxf(rm1, __shfl_xor_sync(0xffffffffu, rm1, 2));

        float nm0 = fmaxf(mi0, rm0), nm1 = fmaxf(mi1, rm1);
        float corr0 = __expf(mi0 - nm0), corr1 = __expf(mi1 - nm1);
        mi0 = nm0; mi1 = nm1;

        float sum0 = 0.f, sum1 = 0.f;
#pragma unroll
        for (int nb = 0; nb < 8; nb++) {
            float p0 = __expf(S[nb][0] - nm0);
            float p1 = __expf(S[nb][1] - nm0);
            float p2 = __expf(S[nb][2] - nm1);
            float p3 = __expf(S[nb][3] - nm1);
            sum0 += p0 + p1; sum1 += p2 + p3;
            S[nb][0] = __uint_as_float(f2tf(p0));
            S[nb][1] = __uint_as_float(f2tf(p1));
            S[nb][2] = __uint_as_float(f2tf(p2));
            S[nb][3] = __uint_as_float(f2tf(p3));
        }
        sum0 += __shfl_xor_sync(0xffffffffu, sum0, 1);
        sum0 += __shfl_xor_sync(0xffffffffu, sum0, 2);
        sum1 += __shfl_xor_sync(0xffffffffu, sum1, 1);
        sum1 += __shfl_xor_sync(0xffffffffu, sum1, 2);
        li0 = li0 * corr0 + sum0;
        li1 = li1 * corr1 + sum1;

        // rescale O
#pragma unroll
        for (int db = 0; db < 4; db++) {
            O[db][0] *= corr0; O[db][1] *= corr0;
            O[db][2] *= corr1; O[db][3] *= corr1;
        }

        // ---- mma2: O(16x32) += P V. A-frag built from S via shuffles ----
#pragma unroll
        for (int ks2 = 0; ks2 < 8; ks2++) {
            float v0 = __shfl_sync(0xffffffffu, S[ks2][0], srcA);
            float v1 = __shfl_sync(0xffffffffu, S[ks2][1], srcA);
            float v2 = __shfl_sync(0xffffffffu, S[ks2][2], srcA);
            float v3 = __shfl_sync(0xffffffffu, S[ks2][3], srcA);
            float w0 = __shfl_sync(0xffffffffu, S[ks2][0], srcB);
            float w1 = __shfl_sync(0xffffffffu, S[ks2][1], srcB);
            float w2 = __shfl_sync(0xffffffffu, S[ks2][2], srcB);
            float w3 = __shfl_sync(0xffffffffu, S[ks2][3], srcB);
            uint32_t a[4];
            a[0] = __float_as_uint(hi ? v1 : v0);
            a[1] = __float_as_uint(hi ? v3 : v2);
            a[2] = __float_as_uint(hi ? w1 : w0);
            a[3] = __float_as_uint(hi ? w3 : w2);
#pragma unroll
            for (int db = 0; db < 4; db++) {
                uint32_t bv[2];
                int vb = (ks2 * 8 + tig) * VS_STR + db * 8 + gid;
                bv[0] = __float_as_uint(Vs[cur][vb]);
                bv[1] = __float_as_uint(Vs[cur][vb + 4 * VS_STR]);
                mma_tf32(O[db], a, bv, O[db]);
            }
        }

        // stage next tile into the other buffer
        if (mt + 1 < NPIX / MT) {
#pragma unroll
            for (int it = 0; it < 2; it++) {
                int i = tid + it * 256;
                int r = i >> 3, c4 = i & 7;
                *(float4*)&Ks[cur ^ 1][r * KS_STR + c4 * 4] = cvt4(kpre[it]);
                *(float4*)&Vs[cur ^ 1][r * VS_STR + c4 * 4] = cvt4(vpre[it]);
            }
        }
        __syncthreads();
    }

    // epilogue
    float inv0 = 1.f / li0, inv1 = 1.f / li1;
    size_t base = (size_t)b * NPIX + (size_t)qt * QT + warp * 16;
#pragma unroll
    for (int db = 0; db < 4; db++) {
        float2 o0, o1;
        o0.x = O[db][0] * inv0; o0.y = O[db][1] * inv0;
        o1.x = O[db][2] * inv1; o1.y = O[db][3] * inv1;
        *(float2*)(g_attn + (base + gid)     * DHEAD + db * 8 + 2 * tig) = o0;
        *(float2*)(g_attn + (base + gid + 8) * DHEAD + db * 8 + 2 * tig) = o1;
    }
}

// ---------------------------------------------------------------------------
// Kernel 3: output projection with tf32 mma.
// A[32768,32] @ Wo[32,256] + bo, ReLU. Grid (256, 2): n-halves of 128.
// ---------------------------------------------------------------------------
__global__ void __launch_bounds__(256) proj_kernel(
    const float* __restrict__ Wo,
    const float* __restrict__ bo,
    float* __restrict__ out)
{
    __shared__ float As[128 * XS_STR];     // 18.4 KB
    __shared__ float Wos[32 * WO_STR];     // 17.4 KB
    __shared__ float bos[128];

    const int tid = threadIdx.x;
    const int warp = tid >> 5, lane = tid & 31;
    const int gid = lane >> 2, tig = lane & 3;
    const int row0 = blockIdx.x * 128;
    const int n0   = blockIdx.y * 128;

    if (tid < 128) bos[tid] = bo[n0 + tid];

    // load A tile (tf32)
#pragma unroll
    for (int it = 0; it < 4; it++) {
        int i = tid + it * 256;
        int r = i >> 3, c4 = i & 7;
        float4 v = *(const float4*)(g_attn + (size_t)(row0 + r) * DHEAD + c4 * 4);
        *(float4*)&As[r * XS_STR + c4 * 4] = cvt4(v);
    }
    // load Wo half (tf32): 32 rows x 128 cols
#pragma unroll
    for (int it = 0; it < 4; it++) {
        int i = tid + it * 256;
        int kk = i >> 5, c4 = i & 31;
        float4 v = *(const float4*)(Wo + (size_t)kk * CIN + n0 + c4 * 4);
        *(float4*)&Wos[kk * WO_STR + c4 * 4] = cvt4(v);
    }
    __syncthreads();

    float acc[16][4];
#pragma unroll
    for (int nb = 0; nb < 16; nb++)
#pragma unroll
        for (int r = 0; r < 4; r++) acc[nb][r] = 0.f;

#pragma unroll
    for (int ks = 0; ks < 4; ks++) {
        uint32_t a[4];
        int ab = (warp * 16 + gid) * XS_STR + ks * 8 + tig;
        a[0] = __float_as_uint(As[ab]);
        a[1] = __float_as_uint(As[ab + 8 * XS_STR]);
        a[2] = __float_as_uint(As[ab + 4]);
        a[3] = __float_as_uint(As[ab + 8 * XS_STR + 4]);
#pragma unroll
        for (int nb = 0; nb < 16; nb++) {
            uint32_t bf[2];
            int wb = (ks * 8 + tig) * WO_STR + nb * 8 + gid;
            bf[0] = __float_as_uint(Wos[wb]);
            bf[1] = __float_as_uint(Wos[wb + 4 * WO_STR]);
            mma_tf32(acc[nb], a, bf, acc[nb]);
        }
    }

    // epilogue: bias + ReLU
#pragma unroll
    for (int nb = 0; nb < 16; nb++) {
        int c = nb * 8 + 2 * tig;
        float b0 = bos[c], b1 = bos[c + 1];
        int r0 = row0 + warp * 16 + gid;
        float2 lo, hi;
        lo.x = fmaxf(acc[nb][0] + b0, 0.f); lo.y = fmaxf(acc[nb][1] + b1, 0.f);
        hi.x = fmaxf(acc[nb][2] + b0, 0.f); hi.y = fmaxf(acc[nb][3] + b1, 0.f);
        *(float2*)(out + (size_t)r0 * CIN + n0 + c)       = lo;
        *(float2*)(out + (size_t)(r0 + 8) * CIN + n0 + c) = hi;
    }
}

// ---------------------------------------------------------------------------
extern "C" void kernel_launch(void* const* d_in, const int* in_sizes, int n_in,
                              void* d_out, int out_size)
{
    const float* x  = (const float*)d_in[0];
    const float* Wq = (const float*)d_in[1];
    const float* bq = (const float*)d_in[2];
    const float* Wk = (const float*)d_in[3];
    const float* bk = (const float*)d_in[4];
    const float* Wv = (const float*)d_in[5];
    const float* bv = (const float*)d_in[6];
    const float* Wo = (const float*)d_in[7];
    const float* bo = (const float*)d_in[8];
    float* out = (float*)d_out;

    qkv_kernel<<<MROWS / 128, 256>>>(x, Wq, bq, Wk, bk, Wv, bv);
    attn_kernel<<<dim3(NPIX / QT, BATCH), 256>>>();
    proj_kernel<<<dim3(MROWS / 128, 2), 256>>>(Wo, bo, out);
}

// round 4
// speedup vs baseline: 7.5132x; 1.8316x over previous
#include <cuda_runtime.h>
#include <cuda_fp16.h>
#include <cstdint>

// Problem constants
#define BATCH 8
#define NPIX  4096          // 64*64
#define CIN   256
#define DHEAD 32
#define MROWS (BATCH*NPIX)  // 32768

#define QT 128              // q rows per attn block (8 warps x 16 rows)
#define MT 64               // k/v rows per inner tile

// smem strides (in halves). 40 halves = 80B rows: 16B aligned, banks 20r%32 CF.
#define TS 40
#define WQS 104             // 208B rows: 16B aligned, banks 20k%32 CF
#define WOS 136             // 272B rows: 16B aligned, banks 4k%32 CF (k<8)

// fp16 scratch (device globals; no runtime allocation allowed)
__device__ __half g_q[MROWS * DHEAD];
__device__ __half g_k[MROWS * DHEAD];
__device__ __half g_v[MROWS * DHEAD];
__device__ __half g_attn[MROWS * DHEAD];

// ---------------------------------------------------------------------------
// helpers
// ---------------------------------------------------------------------------
__device__ __forceinline__ uint32_t pack2(float lo, float hi) {
    __half2 h = __floats2half2_rn(lo, hi);
    return *reinterpret_cast<uint32_t*>(&h);
}

__device__ __forceinline__ void mma_f16(float* d, const uint32_t* a,
                                        uint32_t b0, uint32_t b1, const float* c)
{
    asm("mma.sync.aligned.m16n8k16.row.col.f32.f16.f16.f32 "
        "{%0,%1,%2,%3}, {%4,%5,%6,%7}, {%8,%9}, {%10,%11,%12,%13};"
        : "=f"(d[0]), "=f"(d[1]), "=f"(d[2]), "=f"(d[3])
        : "r"(a[0]), "r"(a[1]), "r"(a[2]), "r"(a[3]),
          "r"(b0), "r"(b1),
          "f"(c[0]), "f"(c[1]), "f"(c[2]), "f"(c[3]));
}

__device__ __forceinline__ void ldsm4(uint32_t* r, uint32_t addr) {
    asm volatile("ldmatrix.sync.aligned.m8n8.x4.shared.b16 {%0,%1,%2,%3}, [%4];"
                 : "=r"(r[0]), "=r"(r[1]), "=r"(r[2]), "=r"(r[3]) : "r"(addr));
}
__device__ __forceinline__ void ldsm4t(uint32_t* r, uint32_t addr) {
    asm volatile("ldmatrix.sync.aligned.m8n8.x4.trans.shared.b16 {%0,%1,%2,%3}, [%4];"
                 : "=r"(r[0]), "=r"(r[1]), "=r"(r[2]), "=r"(r[3]) : "r"(addr));
}

// ---------------------------------------------------------------------------
// Kernel 1: QKV projection, fp16 mma, double-buffered K chunks of 32.
// X[32768,256] @ [Wq|Wk|Wv][256,96] + bias, ReLU -> g_q/g_k/g_v (fp16).
// Block 256 / 8 warps; M tile 128 (warp m16), N = 96 (12 n8 blocks).
// ---------------------------------------------------------------------------
__global__ void __launch_bounds__(256) qkv_kernel(
    const float* __restrict__ x,
    const float* __restrict__ Wq, const float* __restrict__ bq,
    const float* __restrict__ Wk, const float* __restrict__ bk,
    const float* __restrict__ Wv, const float* __restrict__ bv)
{
    __shared__ __half Xs[2][128 * TS];     // 2 x 10 KB
    __shared__ __half Ws[2][32 * WQS];     // 2 x 6.5 KB
    __shared__ float bsm[96];

    const int tid = threadIdx.x;
    const int warp = tid >> 5, lane = tid & 31;
    const int gid = lane >> 2, tig = lane & 3;
    const int row0 = blockIdx.x * 128;

    const uint32_t xs_base = (uint32_t)__cvta_generic_to_shared(&Xs[0][0]);
    const uint32_t ws_base = (uint32_t)__cvta_generic_to_shared(&Ws[0][0]);
    const uint32_t XBUF = 128 * TS * 2;    // bytes per X buffer
    const uint32_t WBUF = 32 * WQS * 2;

    if (tid < 96) bsm[tid] = (tid < 32) ? bq[tid] : (tid < 64 ? bk[tid - 32] : bv[tid - 64]);

    const float* wmat[3] = {Wq, Wk, Wv};

    float acc[12][4];
#pragma unroll
    for (int nb = 0; nb < 12; nb++)
#pragma unroll
        for (int r = 0; r < 4; r++) acc[nb][r] = 0.f;

    // ---- prologue: load chunk 0 ----
    float4 xr[4], wr[3];
#pragma unroll
    for (int it = 0; it < 4; it++) {
        int i = tid + it * 256;
        int r = i >> 3, c4 = i & 7;
        xr[it] = *(const float4*)(x + (size_t)(row0 + r) * CIN + c4 * 4);
    }
#pragma unroll
    for (int m = 0; m < 3; m++) {
        int kk = tid >> 3, c4 = tid & 7;
        wr[m] = *(const float4*)(wmat[m] + (size_t)kk * DHEAD + c4 * 4);
    }
#pragma unroll
    for (int it = 0; it < 4; it++) {
        int i = tid + it * 256;
        int r = i >> 3, c4 = i & 7;
        uint2 p; p.x = pack2(xr[it].x, xr[it].y); p.y = pack2(xr[it].z, xr[it].w);
        *(uint2*)&Xs[0][r * TS + c4 * 4] = p;
    }
#pragma unroll
    for (int m = 0; m < 3; m++) {
        int kk = tid >> 3, c4 = tid & 7;
        uint2 p; p.x = pack2(wr[m].x, wr[m].y); p.y = pack2(wr[m].z, wr[m].w);
        *(uint2*)&Ws[0][kk * WQS + m * 32 + c4 * 4] = p;
    }
    __syncthreads();

    for (int c = 0; c < 8; c++) {
        const int cur = c & 1;

        // prefetch chunk c+1
        if (c + 1 < 8) {
            int kc = (c + 1) * 32;
#pragma unroll
            for (int it = 0; it < 4; it++) {
                int i = tid + it * 256;
                int r = i >> 3, c4 = i & 7;
                xr[it] = *(const float4*)(x + (size_t)(row0 + r) * CIN + kc + c4 * 4);
            }
#pragma unroll
            for (int m = 0; m < 3; m++) {
                int kk = tid >> 3, c4 = tid & 7;
                wr[m] = *(const float4*)(wmat[m] + (size_t)(kc + kk) * DHEAD + c4 * 4);
            }
        }

        // A fragments: 2 LDSM.x4 (ks = 0,1)
        uint32_t a[2][4];
#pragma unroll
        for (int ks = 0; ks < 2; ks++) {
            uint32_t addr = xs_base + cur * XBUF +
                ((warp * 16 + ((lane >> 3) & 1) * 8 + (lane & 7)) * TS) * 2 +
                (ks * 16 + (lane >> 4) * 8) * 2;
            ldsm4(a[ks], addr);
        }
        // B: 12 LDSM.x4.trans, mma
#pragma unroll
        for (int ks = 0; ks < 2; ks++) {
#pragma unroll
            for (int nbp = 0; nbp < 6; nbp++) {
                uint32_t wb[4];
                uint32_t addr = ws_base + cur * WBUF +
                    ((ks * 16 + ((lane >> 3) & 1) * 8 + (lane & 7)) * WQS) * 2 +
                    (nbp * 16 + (lane >> 4) * 8) * 2;
                ldsm4t(wb, addr);
                mma_f16(acc[2 * nbp],     a[ks], wb[0], wb[1], acc[2 * nbp]);
                mma_f16(acc[2 * nbp + 1], a[ks], wb[2], wb[3], acc[2 * nbp + 1]);
            }
        }

        // stage chunk c+1
        if (c + 1 < 8) {
#pragma unroll
            for (int it = 0; it < 4; it++) {
                int i = tid + it * 256;
                int r = i >> 3, c4 = i & 7;
                uint2 p; p.x = pack2(xr[it].x, xr[it].y); p.y = pack2(xr[it].z, xr[it].w);
                *(uint2*)&Xs[cur ^ 1][r * TS + c4 * 4] = p;
            }
#pragma unroll
            for (int m = 0; m < 3; m++) {
                int kk = tid >> 3, c4 = tid & 7;
                uint2 p; p.x = pack2(wr[m].x, wr[m].y); p.y = pack2(wr[m].z, wr[m].w);
                *(uint2*)&Ws[cur ^ 1][kk * WQS + m * 32 + c4 * 4] = p;
            }
        }
        __syncthreads();
    }

    // epilogue: bias + ReLU -> fp16 q/k/v
#pragma unroll
    for (int nb = 0; nb < 12; nb++) {
        int cc = nb * 8 + 2 * tig;
        float b0 = bsm[cc], b1 = bsm[cc + 1];
        int r0 = row0 + warp * 16 + gid;
        __half* dst; int col;
        if (nb < 4)      { dst = g_q; col = cc; }
        else if (nb < 8) { dst = g_k; col = cc - 32; }
        else             { dst = g_v; col = cc - 64; }
        *(uint32_t*)(dst + (size_t)r0 * DHEAD + col) =
            pack2(fmaxf(acc[nb][0] + b0, 0.f), fmaxf(acc[nb][1] + b1, 0.f));
        *(uint32_t*)(dst + (size_t)(r0 + 8) * DHEAD + col) =
            pack2(fmaxf(acc[nb][2] + b0, 0.f), fmaxf(acc[nb][3] + b1, 0.f));
    }
}

// ---------------------------------------------------------------------------
// Kernel 2: flash attention, fp16 mma, ldmatrix operands, zero-copy P
// (mma1 C-frag == mma2 A-frag), double-buffered K/V. Grid (32, 8), 8 warps.
// ---------------------------------------------------------------------------
__global__ void __launch_bounds__(256, 2) attn_kernel()
{
    __shared__ __half Ks[2][MT * TS];   // 2 x 5 KB
    __shared__ __half Vs[2][MT * TS];   // 2 x 5 KB

    const int b   = blockIdx.y;
    const int qt  = blockIdx.x;
    const int tid = threadIdx.x;
    const int warp = tid >> 5, lane = tid & 31;
    const int gid = lane >> 2, tig = lane & 3;

    const uint32_t ks_base = (uint32_t)__cvta_generic_to_shared(&Ks[0][0]);
    const uint32_t vs_base = (uint32_t)__cvta_generic_to_shared(&Vs[0][0]);
    const uint32_t BUF = MT * TS * 2;   // bytes per buffer

    const __half* qg = g_q + ((size_t)b * NPIX + (size_t)qt * QT + warp * 16) * DHEAD;
    const __half* kg = g_k + (size_t)b * NPIX * DHEAD;
    const __half* vg = g_v + (size_t)b * NPIX * DHEAD;

    // Q A-fragments (fp16), loaded once from gmem
    uint32_t qa[2][4];
#pragma unroll
    for (int ks = 0; ks < 2; ks++) {
        qa[ks][0] = *(const uint32_t*)(qg + (size_t)(gid)     * DHEAD + ks * 16 + 2 * tig);
        qa[ks][1] = *(const uint32_t*)(qg + (size_t)(gid + 8) * DHEAD + ks * 16 + 2 * tig);
        qa[ks][2] = *(const uint32_t*)(qg + (size_t)(gid)     * DHEAD + ks * 16 + 8 + 2 * tig);
        qa[ks][3] = *(const uint32_t*)(qg + (size_t)(gid + 8) * DHEAD + ks * 16 + 8 + 2 * tig);
    }

    float O[4][4];
#pragma unroll
    for (int db = 0; db < 4; db++)
#pragma unroll
        for (int r = 0; r < 4; r++) O[db][r] = 0.f;
    float mi0 = -1e30f, mi1 = -1e30f, li0 = 0.f, li1 = 0.f;

    // staging: one uint4 (8 halves) per thread for K and V each
    const int sr = tid >> 2, sc = (tid & 3) * 8;   // row 0..63, col offset in halves
    uint4 kpre, vpre;
    kpre = *(const uint4*)(kg + (size_t)sr * DHEAD + sc);
    vpre = *(const uint4*)(vg + (size_t)sr * DHEAD + sc);
    *(uint4*)&Ks[0][sr * TS + sc] = kpre;
    *(uint4*)&Vs[0][sr * TS + sc] = vpre;
    __syncthreads();

    for (int mt = 0; mt < NPIX / MT; mt++) {
        const int cur = mt & 1;

        // prefetch next tile
        if (mt + 1 < NPIX / MT) {
            kpre = *(const uint4*)(kg + (size_t)((mt + 1) * MT + sr) * DHEAD + sc);
            vpre = *(const uint4*)(vg + (size_t)((mt + 1) * MT + sr) * DHEAD + sc);
        }

        // ---- mma1: S(16x64) = Q K^T ----
        float S[8][4];
#pragma unroll
        for (int nb = 0; nb < 8; nb++) {
#pragma unroll
            for (int r = 0; r < 4; r++) S[nb][r] = 0.f;
            uint32_t kb[4];
            uint32_t addr = ks_base + cur * BUF +
                ((nb * 8 + (lane & 7)) * TS) * 2 + (lane >> 3) * 16;
            ldsm4(kb, addr);                         // [b0k0, b1k0, b0k1, b1k1]
            mma_f16(S[nb], qa[0], kb[0], kb[1], S[nb]);
            mma_f16(S[nb], qa[1], kb[2], kb[3], S[nb]);
        }

        // ---- online softmax (rows gid, gid+8) ----
        float rm0 = -1e30f, rm1 = -1e30f;
#pragma unroll
        for (int nb = 0; nb < 8; nb++) {
            rm0 = fmaxf(rm0, fmaxf(S[nb][0], S[nb][1]));
            rm1 = fmaxf(rm1, fmaxf(S[nb][2], S[nb][3]));
        }
        rm0 = fmaxf(rm0, __shfl_xor_sync(0xffffffffu, rm0, 1));
        rm0 = fmaxf(rm0, __shfl_xor_sync(0xffffffffu, rm0, 2));
        rm1 = fmaxf(rm1, __shfl_xor_sync(0xffffffffu, rm1, 1));
        rm1 = fmaxf(rm1, __shfl_xor_sync(0xffffffffu, rm1, 2));

        float nm0 = fmaxf(mi0, rm0), nm1 = fmaxf(mi1, rm1);
        float corr0 = __expf(mi0 - nm0), corr1 = __expf(mi1 - nm1);
        mi0 = nm0; mi1 = nm1;

        // exp + pack P into mma2 A-fragments (C-frag == A-frag identity)
        uint32_t P[4][4];
        float sum0 = 0.f, sum1 = 0.f;
#pragma unroll
        for (int nb = 0; nb < 8; nb++) {
            float p0 = __expf(S[nb][0] - nm0);
            float p1 = __expf(S[nb][1] - nm0);
            float p2 = __expf(S[nb][2] - nm1);
            float p3 = __expf(S[nb][3] - nm1);
            sum0 += p0 + p1; sum1 += p2 + p3;
            int ks2 = nb >> 1, hi = (nb & 1) * 2;
            P[ks2][hi]     = pack2(p0, p1);
            P[ks2][hi + 1] = pack2(p2, p3);
        }
        sum0 += __shfl_xor_sync(0xffffffffu, sum0, 1);
        sum0 += __shfl_xor_sync(0xffffffffu, sum0, 2);
        sum1 += __shfl_xor_sync(0xffffffffu, sum1, 1);
        sum1 += __shfl_xor_sync(0xffffffffu, sum1, 2);
        li0 = li0 * corr0 + sum0;
        li1 = li1 * corr1 + sum1;

        // rescale O
#pragma unroll
        for (int db = 0; db < 4; db++) {
            O[db][0] *= corr0; O[db][1] *= corr0;
            O[db][2] *= corr1; O[db][3] *= corr1;
        }

        // ---- mma2: O(16x32) += P V ----
#pragma unroll
        for (int ks2 = 0; ks2 < 4; ks2++) {
            // A-frag: P[ks2] regs order {c0(2ks2),c2(2ks2),c0(2ks2+1),c2(2ks2+1)}
            uint32_t a[4];
            a[0] = P[ks2][0]; a[1] = P[ks2][1]; a[2] = P[ks2][2]; a[3] = P[ks2][3];
#pragma unroll
            for (int dbp = 0; dbp < 2; dbp++) {
                uint32_t vb[4];
                uint32_t addr = vs_base + cur * BUF +
                    ((ks2 * 16 + ((lane >> 3) & 1) * 8 + (lane & 7)) * TS) * 2 +
                    dbp * 32 + (lane >> 4) * 16;
                ldsm4t(vb, addr);                    // [b0 db, b1 db, b0 db+1, b1 db+1]
                mma_f16(O[2 * dbp],     a, vb[0], vb[1], O[2 * dbp]);
                mma_f16(O[2 * dbp + 1], a, vb[2], vb[3], O[2 * dbp + 1]);
            }
        }

        // stage next tile
        if (mt + 1 < NPIX / MT) {
            *(uint4*)&Ks[cur ^ 1][sr * TS + sc] = kpre;
            *(uint4*)&Vs[cur ^ 1][sr * TS + sc] = vpre;
        }
        __syncthreads();
    }

    // epilogue: divide by l, fp16 store
    float inv0 = 1.f / li0, inv1 = 1.f / li1;
    size_t base = (size_t)b * NPIX + (size_t)qt * QT + warp * 16;
#pragma unroll
    for (int db = 0; db < 4; db++) {
        *(uint32_t*)(g_attn + (base + gid) * DHEAD + db * 8 + 2 * tig) =
            pack2(O[db][0] * inv0, O[db][1] * inv0);
        *(uint32_t*)(g_attn + (base + gid + 8) * DHEAD + db * 8 + 2 * tig) =
            pack2(O[db][2] * inv1, O[db][3] * inv1);
    }
}

// ---------------------------------------------------------------------------
// Kernel 3: output projection, fp16 mma.
// A[32768,32](fp16) @ Wo[32,256] + bo, ReLU -> out (fp32).
// Grid (256, 2): 128-row x 128-col tiles.
// ---------------------------------------------------------------------------
__global__ void __launch_bounds__(256) proj_kernel(
    const float* __restrict__ Wo,
    const float* __restrict__ bo,
    float* __restrict__ out)
{
    __shared__ __half As[128 * TS];     // 10 KB
    __shared__ __half Wos[32 * WOS];    // 8.5 KB
    __shared__ float bos[128];

    const int tid = threadIdx.x;
    const int warp = tid >> 5, lane = tid & 31;
    const int gid = lane >> 2, tig = lane & 3;
    const int row0 = blockIdx.x * 128;
    const int n0   = blockIdx.y * 128;

    const uint32_t as_base = (uint32_t)__cvta_generic_to_shared(&As[0]);
    const uint32_t wo_base = (uint32_t)__cvta_generic_to_shared(&Wos[0]);

    if (tid < 128) bos[tid] = bo[n0 + tid];

    // load A tile (fp16, 2 uint4 per thread)
#pragma unroll
    for (int it = 0; it < 2; it++) {
        int i = tid + it * 256;
        int r = i >> 2, c8 = (i & 3) * 8;
        *(uint4*)&As[r * TS + c8] =
            *(const uint4*)(g_attn + (size_t)(row0 + r) * DHEAD + c8);
    }
    // load + cvt Wo half (32 x 128)
#pragma unroll
    for (int it = 0; it < 4; it++) {
        int i = tid + it * 256;
        int kk = i >> 5, c4 = i & 31;
        float4 v = *(const float4*)(Wo + (size_t)kk * CIN + n0 + c4 * 4);
        uint2 p; p.x = pack2(v.x, v.y); p.y = pack2(v.z, v.w);
        *(uint2*)&Wos[kk * WOS + c4 * 4] = p;
    }
    __syncthreads();

    float acc[16][4];
#pragma unroll
    for (int nb = 0; nb < 16; nb++)
#pragma unroll
        for (int r = 0; r < 4; r++) acc[nb][r] = 0.f;

    uint32_t a[2][4];
#pragma unroll
    for (int ks = 0; ks < 2; ks++) {
        uint32_t addr = as_base +
            ((warp * 16 + ((lane >> 3) & 1) * 8 + (lane & 7)) * TS) * 2 +
            (ks * 16 + (lane >> 4) * 8) * 2;
        ldsm4(a[ks], addr);
    }
#pragma unroll
    for (int ks = 0; ks < 2; ks++) {
#pragma unroll
        for (int nbp = 0; nbp < 8; nbp++) {
            uint32_t wb[4];
            uint32_t addr = wo_base +
                ((ks * 16 + ((lane >> 3) & 1) * 8 + (lane & 7)) * WOS) * 2 +
                (nbp * 16 + (lane >> 4) * 8) * 2;
            ldsm4t(wb, addr);
            mma_f16(acc[2 * nbp],     a[ks], wb[0], wb[1], acc[2 * nbp]);
            mma_f16(acc[2 * nbp + 1], a[ks], wb[2], wb[3], acc[2 * nbp + 1]);
        }
    }

    // epilogue: bias + ReLU -> fp32 out
#pragma unroll
    for (int nb = 0; nb < 16; nb++) {
        int cc = nb * 8 + 2 * tig;
        float b0 = bos[cc], b1 = bos[cc + 1];
        int r0 = row0 + warp * 16 + gid;
        float2 lo, hi;
        lo.x = fmaxf(acc[nb][0] + b0, 0.f); lo.y = fmaxf(acc[nb][1] + b1, 0.f);
        hi.x = fmaxf(acc[nb][2] + b0, 0.f); hi.y = fmaxf(acc[nb][3] + b1, 0.f);
        *(float2*)(out + (size_t)r0 * CIN + n0 + cc)       = lo;
        *(float2*)(out + (size_t)(r0 + 8) * CIN + n0 + cc) = hi;
    }
}

// ---------------------------------------------------------------------------
extern "C" void kernel_launch(void* const* d_in, const int* in_sizes, int n_in,
                              void* d_out, int out_size)
{
    const float* x  = (const float*)d_in[0];
    const float* Wq = (const float*)d_in[1];
    const float* bq = (const float*)d_in[2];
    const float* Wk = (const float*)d_in[3];
    const float* bk = (const float*)d_in[4];
    const float* Wv = (const float*)d_in[5];
    const float* bv = (const float*)d_in[6];
    const float* Wo = (const float*)d_in[7];
    const float* bo = (const float*)d_in[8];
    float* out = (float*)d_out;

    qkv_kernel<<<MROWS / 128, 256>>>(x, Wq, bq, Wk, bk, Wv, bv);
    attn_kernel<<<dim3(NPIX / QT, BATCH), 256>>>();
    proj_kernel<<<dim3(MROWS / 128, 2), 256>>>(Wo, bo, out);
}

// round 7
// speedup vs baseline: 8.2099x; 1.0927x over previous
#include <cuda_runtime.h>
#include <cuda_fp16.h>
#include <cstdint>

// Problem constants
#define BATCH 8
#define NPIX  4096          // 64*64
#define CIN   256
#define DHEAD 32
#define MROWS (BATCH*NPIX)  // 32768

#define QT 128              // q rows per attn block (8 warps x 16 rows)
#define MT 64               // k/v rows per inner tile

// smem strides (in halves). 40 halves = 80B rows: 16B aligned, banks 20r%32 CF.
#define TS 40
#define WQS 104
#define WOS 136

#define LOG2E 1.4426950408889634f

// fp16 scratch (device globals; no runtime allocation allowed)
__device__ __half g_q[MROWS * DHEAD];
__device__ __half g_k[MROWS * DHEAD];
__device__ __half g_v[MROWS * DHEAD];
__device__ __half g_attn[MROWS * DHEAD];

// ---------------------------------------------------------------------------
// helpers
// ---------------------------------------------------------------------------
__device__ __forceinline__ uint32_t pack2(float lo, float hi) {
    __half2 h = __floats2half2_rn(lo, hi);
    return *reinterpret_cast<uint32_t*>(&h);
}
__device__ __forceinline__ uint32_t h2exp2(uint32_t u) {
    uint32_t r;
    asm("ex2.approx.f16x2 %0, %1;" : "=r"(r) : "r"(u));
    return r;
}

__device__ __forceinline__ void mma_f16(float* d, const uint32_t* a,
                                        uint32_t b0, uint32_t b1, const float* c)
{
    asm("mma.sync.aligned.m16n8k16.row.col.f32.f16.f16.f32 "
        "{%0,%1,%2,%3}, {%4,%5,%6,%7}, {%8,%9}, {%10,%11,%12,%13};"
        : "=f"(d[0]), "=f"(d[1]), "=f"(d[2]), "=f"(d[3])
        : "r"(a[0]), "r"(a[1]), "r"(a[2]), "r"(a[3]),
          "r"(b0), "r"(b1),
          "f"(c[0]), "f"(c[1]), "f"(c[2]), "f"(c[3]));
}

__device__ __forceinline__ void ldsm4(uint32_t* r, uint32_t addr) {
    asm volatile("ldmatrix.sync.aligned.m8n8.x4.shared.b16 {%0,%1,%2,%3}, [%4];"
                 : "=r"(r[0]), "=r"(r[1]), "=r"(r[2]), "=r"(r[3]) : "r"(addr));
}
__device__ __forceinline__ void ldsm4t(uint32_t* r, uint32_t addr) {
    asm volatile("ldmatrix.sync.aligned.m8n8.x4.trans.shared.b16 {%0,%1,%2,%3}, [%4];"
                 : "=r"(r[0]), "=r"(r[1]), "=r"(r[2]), "=r"(r[3]) : "r"(addr));
}

// ---------------------------------------------------------------------------
// Kernel 1: QKV projection, fp16 mma, double-buffered K chunks of 32.
// X[32768,256] @ [Wq|Wk|Wv][256,96] + bias, ReLU -> g_q/g_k/g_v (fp16).
// ---------------------------------------------------------------------------
__global__ void __launch_bounds__(256) qkv_kernel(
    const float* __restrict__ x,
    const float* __restrict__ Wq, const float* __restrict__ bq,
    const float* __restrict__ Wk, const float* __restrict__ bk,
    const float* __restrict__ Wv, const float* __restrict__ bv)
{
    __shared__ __half Xs[2][128 * TS];
    __shared__ __half Ws[2][32 * WQS];
    __shared__ float bsm[96];

    const int tid = threadIdx.x;
    const int warp = tid >> 5, lane = tid & 31;
    const int gid = lane >> 2, tig = lane & 3;
    const int row0 = blockIdx.x * 128;

    const uint32_t xs_base = (uint32_t)__cvta_generic_to_shared(&Xs[0][0]);
    const uint32_t ws_base = (uint32_t)__cvta_generic_to_shared(&Ws[0][0]);
    const uint32_t XBUF = 128 * TS * 2;
    const uint32_t WBUF = 32 * WQS * 2;

    if (tid < 96) bsm[tid] = (tid < 32) ? bq[tid] : (tid < 64 ? bk[tid - 32] : bv[tid - 64]);

    const float* wmat[3] = {Wq, Wk, Wv};

    float acc[12][4];
#pragma unroll
    for (int nb = 0; nb < 12; nb++)
#pragma unroll
        for (int r = 0; r < 4; r++) acc[nb][r] = 0.f;

    float4 xr[4], wr[3];
#pragma unroll
    for (int it = 0; it < 4; it++) {
        int i = tid + it * 256;
        int r = i >> 3, c4 = i & 7;
        xr[it] = *(const float4*)(x + (size_t)(row0 + r) * CIN + c4 * 4);
    }
#pragma unroll
    for (int m = 0; m < 3; m++) {
        int kk = tid >> 3, c4 = tid & 7;
        wr[m] = *(const float4*)(wmat[m] + (size_t)kk * DHEAD + c4 * 4);
    }
#pragma unroll
    for (int it = 0; it < 4; it++) {
        int i = tid + it * 256;
        int r = i >> 3, c4 = i & 7;
        uint2 p; p.x = pack2(xr[it].x, xr[it].y); p.y = pack2(xr[it].z, xr[it].w);
        *(uint2*)&Xs[0][r * TS + c4 * 4] = p;
    }
#pragma unroll
    for (int m = 0; m < 3; m++) {
        int kk = tid >> 3, c4 = tid & 7;
        uint2 p; p.x = pack2(wr[m].x, wr[m].y); p.y = pack2(wr[m].z, wr[m].w);
        *(uint2*)&Ws[0][kk * WQS + m * 32 + c4 * 4] = p;
    }
    __syncthreads();

    for (int c = 0; c < 8; c++) {
        const int cur = c & 1;

        if (c + 1 < 8) {
            int kc = (c + 1) * 32;
#pragma unroll
            for (int it = 0; it < 4; it++) {
                int i = tid + it * 256;
                int r = i >> 3, c4 = i & 7;
                xr[it] = *(const float4*)(x + (size_t)(row0 + r) * CIN + kc + c4 * 4);
            }
#pragma unroll
            for (int m = 0; m < 3; m++) {
                int kk = tid >> 3, c4 = tid & 7;
                wr[m] = *(const float4*)(wmat[m] + (size_t)(kc + kk) * DHEAD + c4 * 4);
            }
        }

        uint32_t a[2][4];
#pragma unroll
        for (int ks = 0; ks < 2; ks++) {
            uint32_t addr = xs_base + cur * XBUF +
                ((warp * 16 + ((lane >> 3) & 1) * 8 + (lane & 7)) * TS) * 2 +
                (ks * 16 + (lane >> 4) * 8) * 2;
            ldsm4(a[ks], addr);
        }
#pragma unroll
        for (int ks = 0; ks < 2; ks++) {
#pragma unroll
            for (int nbp = 0; nbp < 6; nbp++) {
                uint32_t wb[4];
                uint32_t addr = ws_base + cur * WBUF +
                    ((ks * 16 + ((lane >> 3) & 1) * 8 + (lane & 7)) * WQS) * 2 +
                    (nbp * 16 + (lane >> 4) * 8) * 2;
                ldsm4t(wb, addr);
                mma_f16(acc[2 * nbp],     a[ks], wb[0], wb[1], acc[2 * nbp]);
                mma_f16(acc[2 * nbp + 1], a[ks], wb[2], wb[3], acc[2 * nbp + 1]);
            }
        }

        if (c + 1 < 8) {
#pragma unroll
            for (int it = 0; it < 4; it++) {
                int i = tid + it * 256;
                int r = i >> 3, c4 = i & 7;
                uint2 p; p.x = pack2(xr[it].x, xr[it].y); p.y = pack2(xr[it].z, xr[it].w);
                *(uint2*)&Xs[cur ^ 1][r * TS + c4 * 4] = p;
            }
#pragma unroll
            for (int m = 0; m < 3; m++) {
                int kk = tid >> 3, c4 = tid & 7;
                uint2 p; p.x = pack2(wr[m].x, wr[m].y); p.y = pack2(wr[m].z, wr[m].w);
                *(uint2*)&Ws[cur ^ 1][kk * WQS + m * 32 + c4 * 4] = p;
            }
        }
        __syncthreads();
    }

#pragma unroll
    for (int nb = 0; nb < 12; nb++) {
        int cc = nb * 8 + 2 * tig;
        float b0 = bsm[cc], b1 = bsm[cc + 1];
        int r0 = row0 + warp * 16 + gid;
        __half* dst; int col;
        if (nb < 4)      { dst = g_q; col = cc; }
        else if (nb < 8) { dst = g_k; col = cc - 32; }
        else             { dst = g_v; col = cc - 64; }
        *(uint32_t*)(dst + (size_t)r0 * DHEAD + col) =
            pack2(fmaxf(acc[nb][0] + b0, 0.f), fmaxf(acc[nb][1] + b1, 0.f));
        *(uint32_t*)(dst + (size_t)(r0 + 8) * DHEAD + col) =
            pack2(fmaxf(acc[nb][2] + b0, 0.f), fmaxf(acc[nb][3] + b1, 0.f));
    }
}

// ---------------------------------------------------------------------------
// Kernel 2: flash attention.
//  - fp16 mma, ldmatrix operands, zero-copy P (mma1 C-frag == mma2 A-frag)
//  - exps via ex2.approx.f16x2 (2 per MUFU op)
//  - row-sum l accumulated by a 5th mma n-block with constant ones B-frag
// Grid (32, 8), 8 warps, double-buffered K/V.
// ---------------------------------------------------------------------------
__global__ void __launch_bounds__(256, 2) attn_kernel()
{
    __shared__ __half Ks[2][MT * TS];
    __shared__ __half Vs[2][MT * TS];

    const int b   = blockIdx.y;
    const int qt  = blockIdx.x;
    const int tid = threadIdx.x;
    const int warp = tid >> 5, lane = tid & 31;
    const int gid = lane >> 2, tig = lane & 3;

    const uint32_t ks_base = (uint32_t)__cvta_generic_to_shared(&Ks[0][0]);
    const uint32_t vs_base = (uint32_t)__cvta_generic_to_shared(&Vs[0][0]);
    const uint32_t BUF = MT * TS * 2;

    // constant B-fragment for the ones column (l accumulator): col 0 of the
    // extra n8 block is all ones; B-frag col index == gid.
    const uint32_t ones = (gid == 0) ? 0x3C003C00u : 0u;

    const __half* qg = g_q + ((size_t)b * NPIX + (size_t)qt * QT + warp * 16) * DHEAD;
    const __half* kg = g_k + (size_t)b * NPIX * DHEAD;
    const __half* vg = g_v + (size_t)b * NPIX * DHEAD;

    uint32_t qa[2][4];
#pragma unroll
    for (int ks = 0; ks < 2; ks++) {
        qa[ks][0] = *(const uint32_t*)(qg + (size_t)(gid)     * DHEAD + ks * 16 + 2 * tig);
        qa[ks][1] = *(const uint32_t*)(qg + (size_t)(gid + 8) * DHEAD + ks * 16 + 2 * tig);
        qa[ks][2] = *(const uint32_t*)(qg + (size_t)(gid)     * DHEAD + ks * 16 + 8 + 2 * tig);
        qa[ks][3] = *(const uint32_t*)(qg + (size_t)(gid + 8) * DHEAD + ks * 16 + 8 + 2 * tig);
    }

    // O[0..3] = output d-blocks, O[4] = l (row-sum) block
    float O[5][4];
#pragma unroll
    for (int nb = 0; nb < 5; nb++)
#pragma unroll
        for (int r = 0; r < 4; r++) O[nb][r] = 0.f;
    float mi0 = -1e30f, mi1 = -1e30f;

    const int sr = tid >> 2, sc = (tid & 3) * 8;
    uint4 kpre, vpre;
    kpre = *(const uint4*)(kg + (size_t)sr * DHEAD + sc);
    vpre = *(const uint4*)(vg + (size_t)sr * DHEAD + sc);
    *(uint4*)&Ks[0][sr * TS + sc] = kpre;
    *(uint4*)&Vs[0][sr * TS + sc] = vpre;
    __syncthreads();

    for (int mt = 0; mt < NPIX / MT; mt++) {
        const int cur = mt & 1;

        if (mt + 1 < NPIX / MT) {
            kpre = *(const uint4*)(kg + (size_t)((mt + 1) * MT + sr) * DHEAD + sc);
            vpre = *(const uint4*)(vg + (size_t)((mt + 1) * MT + sr) * DHEAD + sc);
        }

        // ---- mma1: S(16x64) = Q K^T ----
        float S[8][4];
#pragma unroll
        for (int nb = 0; nb < 8; nb++) {
#pragma unroll
            for (int r = 0; r < 4; r++) S[nb][r] = 0.f;
            uint32_t kb[4];
            uint32_t addr = ks_base + cur * BUF +
                ((nb * 8 + (lane & 7)) * TS) * 2 + (lane >> 3) * 16;
            ldsm4(kb, addr);
            mma_f16(S[nb], qa[0], kb[0], kb[1], S[nb]);
            mma_f16(S[nb], qa[1], kb[2], kb[3], S[nb]);
        }

        // ---- online softmax (rows gid, gid+8) ----
        float rm0 = -1e30f, rm1 = -1e30f;
#pragma unroll
        for (int nb = 0; nb < 8; nb++) {
            rm0 = fmaxf(rm0, fmaxf(S[nb][0], S[nb][1]));
            rm1 = fmaxf(rm1, fmaxf(S[nb][2], S[nb][3]));
        }
        rm0 = fmaxf(rm0, __shfl_xor_sync(0xffffffffu, rm0, 1));
        rm0 = fmaxf(rm0, __shfl_xor_sync(0xffffffffu, rm0, 2));
        rm1 = fmaxf(rm1, __shfl_xor_sync(0xffffffffu, rm1, 1));
        rm1 = fmaxf(rm1, __shfl_xor_sync(0xffffffffu, rm1, 2));

        float nm0 = fmaxf(mi0, rm0), nm1 = fmaxf(mi1, rm1);
        float corr0 = exp2f((mi0 - nm0) * LOG2E);
        float corr1 = exp2f((mi1 - nm1) * LOG2E);
        mi0 = nm0; mi1 = nm1;
        const float nc0 = nm0 * (-LOG2E), nc1 = nm1 * (-LOG2E);

        // exp in fp16x2, pack directly into mma2 A-fragments (1 FFMA/elem)
        uint32_t P[4][4];
#pragma unroll
        for (int nb = 0; nb < 8; nb++) {
            float u0 = fmaf(S[nb][0], LOG2E, nc0);
            float u1 = fmaf(S[nb][1], LOG2E, nc0);
            float u2 = fmaf(S[nb][2], LOG2E, nc1);
            float u3 = fmaf(S[nb][3], LOG2E, nc1);
            int ks2 = nb >> 1, hi = (nb & 1) * 2;
            P[ks2][hi]     = h2exp2(pack2(u0, u1));
            P[ks2][hi + 1] = h2exp2(pack2(u2, u3));
        }

        // rescale O (incl. l block)
#pragma unroll
        for (int nb = 0; nb < 5; nb++) {
            O[nb][0] *= corr0; O[nb][1] *= corr0;
            O[nb][2] *= corr1; O[nb][3] *= corr1;
        }

        // ---- mma2: O(16x32) += P V ;  l += P @ ones ----
#pragma unroll
        for (int ks2 = 0; ks2 < 4; ks2++) {
            const uint32_t* a = P[ks2];
#pragma unroll
            for (int dbp = 0; dbp < 2; dbp++) {
                uint32_t vb[4];
                uint32_t addr = vs_base + cur * BUF +
                    ((ks2 * 16 + ((lane >> 3) & 1) * 8 + (lane & 7)) * TS) * 2 +
                    dbp * 32 + (lane >> 4) * 16;
                ldsm4t(vb, addr);
                mma_f16(O[2 * dbp],     a, vb[0], vb[1], O[2 * dbp]);
                mma_f16(O[2 * dbp + 1], a, vb[2], vb[3], O[2 * dbp + 1]);
            }
            mma_f16(O[4], a, ones, ones, O[4]);
        }

        if (mt + 1 < NPIX / MT) {
            *(uint4*)&Ks[cur ^ 1][sr * TS + sc] = kpre;
            *(uint4*)&Vs[cur ^ 1][sr * TS + sc] = vpre;
        }
        __syncthreads();
    }

    // epilogue: broadcast l within each quad, divide, fp16 store
    float l0 = __shfl_sync(0xffffffffu, O[4][0], lane & 28);
    float l1 = __shfl_sync(0xffffffffu, O[4][2], lane & 28);
    float inv0 = 1.f / l0, inv1 = 1.f / l1;
    size_t base = (size_t)b * NPIX + (size_t)qt * QT + warp * 16;
#pragma unroll
    for (int db = 0; db < 4; db++) {
        *(uint32_t*)(g_attn + (base + gid) * DHEAD + db * 8 + 2 * tig) =
            pack2(O[db][0] * inv0, O[db][1] * inv0);
        *(uint32_t*)(g_attn + (base + gid + 8) * DHEAD + db * 8 + 2 * tig) =
            pack2(O[db][2] * inv1, O[db][3] * inv1);
    }
}

// ---------------------------------------------------------------------------
// Kernel 3: output projection, fp16 mma.
// ---------------------------------------------------------------------------
__global__ void __launch_bounds__(256) proj_kernel(
    const float* __restrict__ Wo,
    const float* __restrict__ bo,
    float* __restrict__ out)
{
    __shared__ __half As[128 * TS];
    __shared__ __half Wos[32 * WOS];
    __shared__ float bos[128];

    const int tid = threadIdx.x;
    const int warp = tid >> 5, lane = tid & 31;
    const int gid = lane >> 2, tig = lane & 3;
    const int row0 = blockIdx.x * 128;
    const int n0   = blockIdx.y * 128;

    const uint32_t as_base = (uint32_t)__cvta_generic_to_shared(&As[0]);
    const uint32_t wo_base = (uint32_t)__cvta_generic_to_shared(&Wos[0]);

    if (tid < 128) bos[tid] = bo[n0 + tid];

#pragma unroll
    for (int it = 0; it < 2; it++) {
        int i = tid + it * 256;
        int r = i >> 2, c8 = (i & 3) * 8;
        *(uint4*)&As[r * TS + c8] =
            *(const uint4*)(g_attn + (size_t)(row0 + r) * DHEAD + c8);
    }
#pragma unroll
    for (int it = 0; it < 4; it++) {
        int i = tid + it * 256;
        int kk = i >> 5, c4 = i & 31;
        float4 v = *(const float4*)(Wo + (size_t)kk * CIN + n0 + c4 * 4);
        uint2 p; p.x = pack2(v.x, v.y); p.y = pack2(v.z, v.w);
        *(uint2*)&Wos[kk * WOS + c4 * 4] = p;
    }
    __syncthreads();

    float acc[16][4];
#pragma unroll
    for (int nb = 0; nb < 16; nb++)
#pragma unroll
        for (int r = 0; r < 4; r++) acc[nb][r] = 0.f;

    uint32_t a[2][4];
#pragma unroll
    for (int ks = 0; ks < 2; ks++) {
        uint32_t addr = as_base +
            ((warp * 16 + ((lane >> 3) & 1) * 8 + (lane & 7)) * TS) * 2 +
            (ks * 16 + (lane >> 4) * 8) * 2;
        ldsm4(a[ks], addr);
    }
#pragma unroll
    for (int ks = 0; ks < 2; ks++) {
#pragma unroll
        for (int nbp = 0; nbp < 8; nbp++) {
            uint32_t wb[4];
            uint32_t addr = wo_base +
                ((ks * 16 + ((lane >> 3) & 1) * 8 + (lane & 7)) * WOS) * 2 +
                (nbp * 16 + (lane >> 4) * 8) * 2;
            ldsm4t(wb, addr);
            mma_f16(acc[2 * nbp],     a[ks], wb[0], wb[1], acc[2 * nbp]);
            mma_f16(acc[2 * nbp + 1], a[ks], wb[2], wb[3], acc[2 * nbp + 1]);
        }
    }

#pragma unroll
    for (int nb = 0; nb < 16; nb++) {
        int cc = nb * 8 + 2 * tig;
        float b0 = bos[cc], b1 = bos[cc + 1];
        int r0 = row0 + warp * 16 + gid;
        float2 lo, hi;
        lo.x = fmaxf(acc[nb][0] + b0, 0.f); lo.y = fmaxf(acc[nb][1] + b1, 0.f);
        hi.x = fmaxf(acc[nb][2] + b0, 0.f); hi.y = fmaxf(acc[nb][3] + b1, 0.f);
        *(float2*)(out + (size_t)r0 * CIN + n0 + cc)       = lo;
        *(float2*)(out + (size_t)(r0 + 8) * CIN + n0 + cc) = hi;
    }
}

// ---------------------------------------------------------------------------
extern "C" void kernel_launch(void* const* d_in, const int* in_sizes, int n_in,
                              void* d_out, int out_size)
{
    const float* x  = (const float*)d_in[0];
    const float* Wq = (const float*)d_in[1];
    const float* bq = (const float*)d_in[2];
    const float* Wk = (const float*)d_in[3];
    const float* bk = (const float*)d_in[4];
    const float* Wv = (const float*)d_in[5];
    const float* bv = (const float*)d_in[6];
    const float* Wo = (const float*)d_in[7];
    const float* bo = (const float*)d_in[8];
    float* out = (float*)d_out;

    qkv_kernel<<<MROWS / 128, 256>>>(x, Wq, bq, Wk, bk, Wv, bv);
    attn_kernel<<<dim3(NPIX / QT, BATCH), 256>>>();
    proj_kernel<<<dim3(MROWS / 128, 2), 256>>>(Wo, bo, out);
}